// round 17
// baseline (speedup 1.0000x reference)
#include <cuda_runtime.h>
#include <cuda_bf16.h>
#include <cuda_fp16.h>

// Problem constants
#define B_  4
#define F_  5
#define P_  920
#define N_  4600          // F_*P_
#define C_  512
#define H_  8
#define DH_ 64
#define M_  (B_*N_)       // 18400
#define MKV_ (M_*F_)      // 92000
#define OUT1_ 9420800     // first tuple output element count

#define KPACK 256         // packets per 512-elem row
#define PP_   460         // packets per 920-elem row

typedef unsigned int u32;

// ---------------- scratch (static device globals; no allocations) -----------
static __device__ uint2 g_xh2   [(size_t)M_ * KPACK];          // x fp16 hi/lo packets
static __device__ u32   g_qh    [(size_t)M_ * KPACK];          // Q fp16 single
static __device__ u32   g_kh    [(size_t)M_ * KPACK];          // K fp16 single
static __device__ u32   g_vh    [(size_t)M_ * KPACK];          // V fp16 single
static __device__ float g_scores[(size_t)B_ * N_ * N_];
static __device__ u32   g_attn1h[(size_t)B_ * N_ * (F_*PP_)];  // attn1 fp16 single
static __device__ u32   g_vt    [(size_t)B_ * F_ * C_ * PP_];  // V^T fp16 single
static __device__ uint2 g_xosp  [(size_t)M_ * F_ * KPACK];     // xo bf16 packets
static __device__ uint2 g_xdsp  [(size_t)M_ * KPACK];
static __device__ uint2 g_q2sp  [(size_t)M_ * KPACK];
static __device__ float g_G     [(size_t)H_ * M_ * C_];
static __device__ uint2 g_xbar  [(size_t)H_ * M_ * KPACK];     // per-head weighted xo
static __device__ uint2 g_out2sp[(size_t)M_ * KPACK];
static __device__ u32   g_wqkvh [1536 * KPACK];                // W_qkv^T fp16 single
static __device__ uint2 g_wq2t  [ 512 * KPACK];
static __device__ uint2 g_wkG   [H_ * 512 * 32];
static __device__ uint2 g_wvt   [ 512 * KPACK];                // per-head contiguous
static __device__ uint2 g_wprojt[ 512 * KPACK];

// ---------------- bf16 helpers ------------------------------------------------
__device__ __forceinline__ unsigned pack_bf2(__nv_bfloat16 a, __nv_bfloat16 b) {
    __nv_bfloat162 t; t.x = a; t.y = b;
    return *reinterpret_cast<unsigned*>(&t);
}
__device__ __forceinline__ uint2 split2(float a, float b) {
    __nv_bfloat16 h0 = __float2bfloat16_rn(a);
    __nv_bfloat16 h1 = __float2bfloat16_rn(b);
    __nv_bfloat16 l0 = __float2bfloat16_rn(a - __bfloat162float(h0));
    __nv_bfloat16 l1 = __float2bfloat16_rn(b - __bfloat162float(h1));
    uint2 e; e.x = pack_bf2(h0, h1); e.y = pack_bf2(l0, l1);
    return e;
}
__device__ __forceinline__ float2 unsplit2(uint2 pk) {
    __nv_bfloat162 h2 = *reinterpret_cast<__nv_bfloat162*>(&pk.x);
    __nv_bfloat162 l2 = *reinterpret_cast<__nv_bfloat162*>(&pk.y);
    float2 r;
    r.x = __bfloat162float(h2.x) + __bfloat162float(l2.x);
    r.y = __bfloat162float(h2.y) + __bfloat162float(l2.y);
    return r;
}

// ---------------- fp16 helpers -------------------------------------------------
__device__ __forceinline__ u32 packh(__half a, __half b) {
    __half2 t; t.x = a; t.y = b;
    return *reinterpret_cast<u32*>(&t);
}
__device__ __forceinline__ u32 h2pack(float a, float b) {
    return packh(__float2half_rn(a), __float2half_rn(b));
}
__device__ __forceinline__ uint2 h2split2(float a, float b) {
    __half h0 = __float2half_rn(a), h1 = __float2half_rn(b);
    __half l0 = __float2half_rn(a - __half2float(h0));
    __half l1 = __float2half_rn(b - __half2float(h1));
    uint2 e; e.x = packh(h0, h1); e.y = packh(l0, l1);
    return e;
}

__device__ __forceinline__ void mma_bf16(float* c, const unsigned* a, const unsigned* b) {
    asm volatile(
        "mma.sync.aligned.m16n8k16.row.col.f32.bf16.bf16.f32 "
        "{%0,%1,%2,%3}, {%4,%5,%6,%7}, {%8,%9}, {%0,%1,%2,%3};"
        : "+f"(c[0]), "+f"(c[1]), "+f"(c[2]), "+f"(c[3])
        : "r"(a[0]), "r"(a[1]), "r"(a[2]), "r"(a[3]),
          "r"(b[0]), "r"(b[1]));
}
__device__ __forceinline__ void mma_f16(float* c, const unsigned* a, const unsigned* b) {
    asm volatile(
        "mma.sync.aligned.m16n8k16.row.col.f32.f16.f16.f32 "
        "{%0,%1,%2,%3}, {%4,%5,%6,%7}, {%8,%9}, {%0,%1,%2,%3};"
        : "+f"(c[0]), "+f"(c[1]), "+f"(c[2]), "+f"(c[3])
        : "r"(a[0]), "r"(a[1]), "r"(a[2]), "r"(a[3]),
          "r"(b[0]), "r"(b[1]));
}

// ---------------- bf16x3 GEMM (gemm_sp) ----------------------------------------
// C = alpha * A x B^T, bf16 split-packet operands. Block 128 x (32*NT) x 32,
// 8 warps (2x4), 3-stage cp.async, xor-swizzled smem.
// EPI: 0 fp32 (float2 stores; requires N even); 1 bf16 packets; 2 proj permute+bias.
#define TILE_A_U 2048

__device__ __forceinline__ int sidx(int r, int kp) {
    return r * 16 + ((((kp >> 1) ^ (r & 7)) << 1) | (kp & 1));
}

template<int EPI, int NT>
__global__ __launch_bounds__(256)
void gemm_sp(const uint2* __restrict__ A,
             const uint2* __restrict__ B,
             void* __restrict__ Cv,
             int M, int N, int K,
             int ldap, int ldbp, int ldc,
             int Z2,
             long sA1, long sA2, long sB1, long sB2,
             long sC1, long sC2,
             float alpha, const float* __restrict__ bias)
{
    constexpr int BN       = 32 * NT;
    constexpr int TILE_B_U = BN * 16;
    constexpr int STAGE_U  = TILE_A_U + TILE_B_U;

    extern __shared__ __align__(16) unsigned char dsm[];
    uint2* sm = reinterpret_cast<uint2*>(dsm);

    const int z  = blockIdx.z;
    const int zb = z / Z2, zf = z % Z2;
    A += (long)zb * sA1 + (long)zf * sA2;
    B += (long)zb * sB1 + (long)zf * sB2;
    float* Cf = (float*)Cv + (long)zb * sC1 + (long)zf * sC2;

    const int bm = blockIdx.y * 128;
    const int bn = blockIdx.x * BN;
    const int tid  = threadIdx.x;
    const int lane = tid & 31;
    const int gid  = lane >> 2;
    const int tig  = lane & 3;
    const int wid  = tid >> 5;
    const int wm   = wid >> 2;
    const int wn   = wid & 3;

    const int Kp = K >> 1;
    const int kt = (Kp + 15) >> 4;

    float acc[4][NT][4];
#pragma unroll
    for (int i = 0; i < 4; i++)
#pragma unroll
        for (int j = 0; j < NT; j++)
#pragma unroll
            for (int t = 0; t < 4; t++) acc[i][j][t] = 0.f;

    auto issue = [&](int buf, int ktile) {
        uint2* sA = sm + buf * STAGE_U;
        uint2* sB = sA + TILE_A_U;
        const int kp0 = ktile * 16;
#pragma unroll
        for (int i = 0; i < 4; i++) {
            int lin = i * 256 + tid;
            int row = lin >> 3, ch = lin & 7;
            int grow = bm + row;
            int gkp  = kp0 + ch * 2;
            bool v = (grow < M) && (gkp < Kp);
            const uint2* src = A + (long)(v ? grow : 0) * ldap + (v ? gkp : 0);
            unsigned sa = (unsigned)__cvta_generic_to_shared(
                &sA[row * 16 + ((ch ^ (row & 7)) << 1)]);
            unsigned sz = v ? 16u : 0u;
            asm volatile("cp.async.cg.shared.global [%0], [%1], 16, %2;\n"
                         :: "r"(sa), "l"(src), "r"(sz));
        }
#pragma unroll
        for (int i = 0; i < NT; i++) {
            int lin = i * 256 + tid;
            int row = lin >> 3, ch = lin & 7;
            int grow = bn + row;
            int gkp  = kp0 + ch * 2;
            bool v = (grow < N) && (gkp < Kp);
            const uint2* src = B + (long)(v ? grow : 0) * ldbp + (v ? gkp : 0);
            unsigned sa = (unsigned)__cvta_generic_to_shared(
                &sB[row * 16 + ((ch ^ (row & 7)) << 1)]);
            unsigned sz = v ? 16u : 0u;
            asm volatile("cp.async.cg.shared.global [%0], [%1], 16, %2;\n"
                         :: "r"(sa), "l"(src), "r"(sz));
        }
        asm volatile("cp.async.commit_group;\n" ::: "memory");
    };

    issue(0, 0);
    if (kt > 1) issue(1, 1); else asm volatile("cp.async.commit_group;\n" ::: "memory");

    const int r0 = wm * 64 + gid;
    const int c0 = wn * (8 * NT) + gid;

    int buf = 0;
    for (int it = 0; it < kt; it++) {
        asm volatile("cp.async.wait_group 1;\n" ::: "memory");
        __syncthreads();

        if (it + 2 < kt) issue((buf + 2) % 3, it + 2);
        else asm volatile("cp.async.commit_group;\n" ::: "memory");

        const uint2* sA = sm + buf * STAGE_U;
        const uint2* sB = sA + TILE_A_U;

#pragma unroll
        for (int ks = 0; ks < 2; ks++) {
            const int kpb = ks * 8;
            unsigned ah[4][4], al[4][4];
#pragma unroll
            for (int mt = 0; mt < 4; mt++) {
                int r = r0 + mt * 16;
                uint2 e00 = sA[sidx(r,     kpb + tig)];
                uint2 e10 = sA[sidx(r + 8, kpb + tig)];
                uint2 e01 = sA[sidx(r,     kpb + tig + 4)];
                uint2 e11 = sA[sidx(r + 8, kpb + tig + 4)];
                ah[mt][0] = e00.x; ah[mt][1] = e10.x; ah[mt][2] = e01.x; ah[mt][3] = e11.x;
                al[mt][0] = e00.y; al[mt][1] = e10.y; al[mt][2] = e01.y; al[mt][3] = e11.y;
            }
#pragma unroll
            for (int nt = 0; nt < NT; nt++) {
                int c = c0 + nt * 8;
                uint2 f0 = sB[sidx(c, kpb + tig)];
                uint2 f1 = sB[sidx(c, kpb + tig + 4)];
                unsigned bh[2] = { f0.x, f1.x };
                unsigned bl[2] = { f0.y, f1.y };
#pragma unroll
                for (int mt = 0; mt < 4; mt++) {
                    mma_bf16(acc[mt][nt], al[mt], bh);
                    mma_bf16(acc[mt][nt], ah[mt], bl);
                    mma_bf16(acc[mt][nt], ah[mt], bh);
                }
            }
        }
        buf++; if (buf == 3) buf = 0;
    }

#pragma unroll
    for (int mt = 0; mt < 4; mt++) {
#pragma unroll
        for (int nt = 0; nt < NT; nt++) {
            int row = bm + wm * 64 + mt * 16 + gid;
            int col = bn + wn * (8 * NT) + nt * 8 + tig * 2;
            float v0 = alpha * acc[mt][nt][0];
            float v1 = alpha * acc[mt][nt][1];
            float v2 = alpha * acc[mt][nt][2];
            float v3 = alpha * acc[mt][nt][3];
            if (EPI == 0) {
                if (row < M && col < N)
                    *reinterpret_cast<float2*>(&Cf[(long)row * ldc + col]) =
                        make_float2(v0, v1);
                if (row + 8 < M && col < N)
                    *reinterpret_cast<float2*>(&Cf[(long)(row + 8) * ldc + col]) =
                        make_float2(v2, v3);
            } else if (EPI == 1) {
                uint2* Cp = reinterpret_cast<uint2*>(Cf);
                int ldcp = ldc >> 1;
                if (row < M && col < N)
                    Cp[(long)row * ldcp + (col >> 1)] = split2(v0, v1);
                if (row + 8 < M && col < N)
                    Cp[(long)(row + 8) * ldcp + (col >> 1)] = split2(v2, v3);
            } else {
                if (row < M && col < N) {
                    int b = row / N_, s = row % N_;
                    int f = s / P_,  p = s % P_;
                    float* o = Cf + (long)p * (B_ * F_ * C_) + ((long)b * F_ + f) * C_ + col;
                    *reinterpret_cast<float2*>(o) =
                        make_float2(v0 + bias[col], v1 + bias[col + 1]);
                }
                if (row + 8 < M && col < N) {
                    int r2 = row + 8;
                    int b = r2 / N_, s = r2 % N_;
                    int f = s / P_,  p = s % P_;
                    float* o = Cf + (long)p * (B_ * F_ * C_) + ((long)b * F_ + f) * C_ + col;
                    *reinterpret_cast<float2*>(o) =
                        make_float2(v2 + bias[col], v3 + bias[col + 1]);
                }
            }
        }
    }
}

// ---------------- fp16 2-mult GEMM (gemm_h2) ------------------------------------
// A = fp16 hi/lo packets (uint2), B = fp16 single plane (u32).
// Columns >= qcols use 1-mult (hi plane only); columns < qcols use 2-mult.
// EPI 3: qkv splitter -> Q fp16 single / K fp16 / V fp16.
#define H2_TILE_A_U 2048
#define H2_BSTRIDE  20
#define H2_TILE_B_W (256 * H2_BSTRIDE)
#define H2_STAGE_B  (H2_TILE_A_U * 8 + H2_TILE_B_W * 4)   // 36864
#define H2_SMEM     (3 * H2_STAGE_B)                      // 110592

__global__ __launch_bounds__(256)
void gemm_h2(const uint2* __restrict__ A,
             const u32* __restrict__ B,
             u32* __restrict__ qout,
             u32* __restrict__ kout, u32* __restrict__ vout,
             int M, int N, int K,
             int ldap, int ldbp,
             float alpha, int qcols)
{
    extern __shared__ __align__(16) unsigned char dsm[];

    const int bm = blockIdx.y * 128;
    const int bn = blockIdx.x * 256;
    const int tid  = threadIdx.x;
    const int lane = tid & 31;
    const int gid  = lane >> 2;
    const int tig  = lane & 3;
    const int wid  = tid >> 5;
    const int wm   = wid >> 2;
    const int wn   = wid & 3;

    const bool two = (bn < qcols);

    const int Kp = K >> 1;
    const int kt = (Kp + 15) >> 4;

    float acc[4][8][4];
#pragma unroll
    for (int i = 0; i < 4; i++)
#pragma unroll
        for (int j = 0; j < 8; j++)
#pragma unroll
            for (int t = 0; t < 4; t++) acc[i][j][t] = 0.f;

    auto issue = [&](int buf, int ktile) {
        uint2* sA = reinterpret_cast<uint2*>(dsm + buf * H2_STAGE_B);
        u32*   sB = reinterpret_cast<u32*>(dsm + buf * H2_STAGE_B + H2_TILE_A_U * 8);
        const int kp0 = ktile * 16;
#pragma unroll
        for (int i = 0; i < 4; i++) {
            int lin = i * 256 + tid;
            int row = lin >> 3, ch = lin & 7;
            int grow = bm + row;
            int gkp  = kp0 + ch * 2;
            bool v = (grow < M) && (gkp < Kp);
            const uint2* src = A + (long)(v ? grow : 0) * ldap + (v ? gkp : 0);
            unsigned sa = (unsigned)__cvta_generic_to_shared(
                &sA[row * 16 + ((ch ^ (row & 7)) << 1)]);
            unsigned sz = v ? 16u : 0u;
            asm volatile("cp.async.cg.shared.global [%0], [%1], 16, %2;\n"
                         :: "r"(sa), "l"(src), "r"(sz));
        }
#pragma unroll
        for (int i = 0; i < 4; i++) {
            int lin = i * 256 + tid;
            int row = lin >> 2, j = lin & 3;
            int grow = bn + row;
            int gkp  = kp0 + j * 4;
            bool v = (grow < N) && (gkp < Kp);
            const u32* src = B + (long)(v ? grow : 0) * ldbp + (v ? gkp : 0);
            unsigned sa = (unsigned)__cvta_generic_to_shared(
                &sB[row * H2_BSTRIDE + j * 4]);
            unsigned sz = v ? 16u : 0u;
            asm volatile("cp.async.cg.shared.global [%0], [%1], 16, %2;\n"
                         :: "r"(sa), "l"(src), "r"(sz));
        }
        asm volatile("cp.async.commit_group;\n" ::: "memory");
    };

    issue(0, 0);
    if (kt > 1) issue(1, 1); else asm volatile("cp.async.commit_group;\n" ::: "memory");

    const int r0 = wm * 64 + gid;
    const int c0 = wn * 64 + gid;

    int buf = 0;
    for (int it = 0; it < kt; it++) {
        asm volatile("cp.async.wait_group 1;\n" ::: "memory");
        __syncthreads();

        if (it + 2 < kt) issue((buf + 2) % 3, it + 2);
        else asm volatile("cp.async.commit_group;\n" ::: "memory");

        const uint2* sA = reinterpret_cast<const uint2*>(dsm + buf * H2_STAGE_B);
        const u32*   sB = reinterpret_cast<const u32*>(dsm + buf * H2_STAGE_B + H2_TILE_A_U * 8);

#pragma unroll
        for (int ks = 0; ks < 2; ks++) {
            const int kpb = ks * 8;
            unsigned ah[4][4], al[4][4];
#pragma unroll
            for (int mt = 0; mt < 4; mt++) {
                int r = r0 + mt * 16;
                uint2 e00 = sA[sidx(r,     kpb + tig)];
                uint2 e10 = sA[sidx(r + 8, kpb + tig)];
                uint2 e01 = sA[sidx(r,     kpb + tig + 4)];
                uint2 e11 = sA[sidx(r + 8, kpb + tig + 4)];
                ah[mt][0] = e00.x; ah[mt][1] = e10.x; ah[mt][2] = e01.x; ah[mt][3] = e11.x;
                al[mt][0] = e00.y; al[mt][1] = e10.y; al[mt][2] = e01.y; al[mt][3] = e11.y;
            }
            if (two) {
#pragma unroll
                for (int nt = 0; nt < 8; nt++) {
                    int cb = (c0 + nt * 8) * H2_BSTRIDE;
                    unsigned b2[2] = { sB[cb + kpb + tig], sB[cb + kpb + tig + 4] };
#pragma unroll
                    for (int mt = 0; mt < 4; mt++) {
                        mma_f16(acc[mt][nt], al[mt], b2);
                        mma_f16(acc[mt][nt], ah[mt], b2);
                    }
                }
            } else {
#pragma unroll
                for (int nt = 0; nt < 8; nt++) {
                    int cb = (c0 + nt * 8) * H2_BSTRIDE;
                    unsigned b2[2] = { sB[cb + kpb + tig], sB[cb + kpb + tig + 4] };
#pragma unroll
                    for (int mt = 0; mt < 4; mt++)
                        mma_f16(acc[mt][nt], ah[mt], b2);
                }
            }
        }
        buf++; if (buf == 3) buf = 0;
    }

#pragma unroll
    for (int mt = 0; mt < 4; mt++) {
#pragma unroll
        for (int nt = 0; nt < 8; nt++) {
            int row = bm + wm * 64 + mt * 16 + gid;
            int col = bn + wn * 64 + nt * 8 + tig * 2;
            float v0 = alpha * acc[mt][nt][0];
            float v1 = alpha * acc[mt][nt][1];
            float v2 = alpha * acc[mt][nt][2];
            float v3 = alpha * acc[mt][nt][3];
            int kp = col >> 1;
            if (row < M && col < N) {
                if (col < 512)       qout[(long)row * KPACK + kp]        = h2pack(v0, v1);
                else if (col < 1024) kout[(long)row * KPACK + kp - 256]  = h2pack(v0, v1);
                else                 vout[(long)row * KPACK + kp - 512]  = h2pack(v0, v1);
            }
            if (row + 8 < M && col < N) {
                long r2 = row + 8;
                if (col < 512)       qout[r2 * KPACK + kp]        = h2pack(v2, v3);
                else if (col < 1024) kout[r2 * KPACK + kp - 256]  = h2pack(v2, v3);
                else                 vout[r2 * KPACK + kp - 512]  = h2pack(v2, v3);
            }
        }
    }
}

// ---------------- fp16 1-mult GEMM (gemm_h1) ------------------------------------
// A = fp16 single plane (u32), B = fp16 single plane (u32). 1 HMMA per acc.
// 512 threads / 16 warps (2m x 8n), warp tile 64x32.
// 4-stage cp.async pipeline with wait_group 2: the sync cadence no longer sits
// on the critical path of the newest load (R16 showed the kernel is
// sync-cadence bound, not eligible-warp bound).
// EPI: 0 fp32 (float2 stores; N even); 1 bf16 split-packet C + diag side-write.
#define H1_STRIDE  20
#define H1_TILE_A_W (128 * H1_STRIDE)
#define H1_TILE_B_W (256 * H1_STRIDE)
#define H1_STAGE_B  ((H1_TILE_A_W + H1_TILE_B_W) * 4)     // 30720
#define H1_STAGES   4
#define H1_SMEM     (H1_STAGES * H1_STAGE_B)              // 122880
#define H1_THREADS  512

template<int EPI>
__global__ __launch_bounds__(H1_THREADS)
void gemm_h1(const u32* __restrict__ A,
             const u32* __restrict__ B,
             void* __restrict__ Cv,
             uint2* __restrict__ xdiag,
             int M, int N, int K,
             int ldap, int ldbp, int ldc,
             int Z2,
             long sA1, long sA2, long sB1, long sB2,
             long sC1, long sC2,
             float alpha)
{
    extern __shared__ __align__(16) unsigned char dsm[];

    const int z  = blockIdx.z;
    const int zb = z / Z2, zf = z % Z2;
    A += (long)zb * sA1 + (long)zf * sA2;
    B += (long)zb * sB1 + (long)zf * sB2;
    float* Cf = (float*)Cv + (long)zb * sC1 + (long)zf * sC2;

    const int bm = blockIdx.y * 128;
    const int bn = blockIdx.x * 256;
    const int tid  = threadIdx.x;
    const int lane = tid & 31;
    const int gid  = lane >> 2;
    const int tig  = lane & 3;
    const int wid  = tid >> 5;          // 0..15
    const int wm   = wid >> 3;          // 0..1  (64-row slab)
    const int wn   = wid & 7;           // 0..7  (32-col slab)

    const int Kp = K >> 1;
    const int kt = (Kp + 15) >> 4;

    float acc[4][4][4];
#pragma unroll
    for (int i = 0; i < 4; i++)
#pragma unroll
        for (int j = 0; j < 4; j++)
#pragma unroll
            for (int t = 0; t < 4; t++) acc[i][j][t] = 0.f;

    auto issue = [&](int buf, int ktile) {
        u32* sA = reinterpret_cast<u32*>(dsm + buf * H1_STAGE_B);
        u32* sB = sA + H1_TILE_A_W;
        const int kp0 = ktile * 16;
        // A: 128 rows x 4 chunks of 16B = 512 chunks, 1/thread
        {
            int lin = tid;
            int row = lin >> 2, j = lin & 3;
            int grow = bm + row;
            int gkp  = kp0 + j * 4;
            bool v = (grow < M) && (gkp < Kp);
            const u32* src = A + (long)(v ? grow : 0) * ldap + (v ? gkp : 0);
            unsigned sa = (unsigned)__cvta_generic_to_shared(
                &sA[row * H1_STRIDE + j * 4]);
            unsigned sz = v ? 16u : 0u;
            asm volatile("cp.async.cg.shared.global [%0], [%1], 16, %2;\n"
                         :: "r"(sa), "l"(src), "r"(sz));
        }
        // B: 256 rows x 4 chunks = 1024 chunks, 2/thread
#pragma unroll
        for (int i = 0; i < 2; i++) {
            int lin = i * H1_THREADS + tid;
            int row = lin >> 2, j = lin & 3;
            int grow = bn + row;
            int gkp  = kp0 + j * 4;
            bool v = (grow < N) && (gkp < Kp);
            const u32* src = B + (long)(v ? grow : 0) * ldbp + (v ? gkp : 0);
            unsigned sa = (unsigned)__cvta_generic_to_shared(
                &sB[row * H1_STRIDE + j * 4]);
            unsigned sz = v ? 16u : 0u;
            asm volatile("cp.async.cg.shared.global [%0], [%1], 16, %2;\n"
                         :: "r"(sa), "l"(src), "r"(sz));
        }
        asm volatile("cp.async.commit_group;\n" ::: "memory");
    };

    // prologue: 3 tiles in flight
    issue(0, 0);
    if (kt > 1) issue(1, 1); else asm volatile("cp.async.commit_group;\n" ::: "memory");
    if (kt > 2) issue(2, 2); else asm volatile("cp.async.commit_group;\n" ::: "memory");

    const int r0 = wm * 64 + gid;
    const int c0 = wn * 32 + gid;

    int buf = 0;
    for (int it = 0; it < kt; it++) {
        asm volatile("cp.async.wait_group 2;\n" ::: "memory");
        __syncthreads();

        if (it + 3 < kt) issue((buf + 3) & 3, it + 3);
        else asm volatile("cp.async.commit_group;\n" ::: "memory");

        const u32* sA = reinterpret_cast<const u32*>(dsm + buf * H1_STAGE_B);
        const u32* sB = sA + H1_TILE_A_W;

#pragma unroll
        for (int ks = 0; ks < 2; ks++) {
            const int kpb = ks * 8;
            unsigned a[4][4];
#pragma unroll
            for (int mt = 0; mt < 4; mt++) {
                int r = r0 + mt * 16;
                a[mt][0] = sA[(r)     * H1_STRIDE + kpb + tig];
                a[mt][1] = sA[(r + 8) * H1_STRIDE + kpb + tig];
                a[mt][2] = sA[(r)     * H1_STRIDE + kpb + tig + 4];
                a[mt][3] = sA[(r + 8) * H1_STRIDE + kpb + tig + 4];
            }
#pragma unroll
            for (int nt = 0; nt < 4; nt++) {
                int cb = (c0 + nt * 8) * H1_STRIDE;
                unsigned b2[2] = { sB[cb + kpb + tig], sB[cb + kpb + tig + 4] };
#pragma unroll
                for (int mt = 0; mt < 4; mt++)
                    mma_f16(acc[mt][nt], a[mt], b2);
            }
        }
        buf = (buf + 1) & 3;
    }

    const int dlo = zf * P_;
    const int dhi = dlo + P_;

#pragma unroll
    for (int mt = 0; mt < 4; mt++) {
#pragma unroll
        for (int nt = 0; nt < 4; nt++) {
            int row = bm + wm * 64 + mt * 16 + gid;
            int col = bn + wn * 32 + nt * 8 + tig * 2;
            float v0 = alpha * acc[mt][nt][0];
            float v1 = alpha * acc[mt][nt][1];
            float v2 = alpha * acc[mt][nt][2];
            float v3 = alpha * acc[mt][nt][3];
            if (EPI == 0) {
                if (row < M && col < N)
                    *reinterpret_cast<float2*>(&Cf[(long)row * ldc + col]) =
                        make_float2(v0, v1);
                if (row + 8 < M && col < N)
                    *reinterpret_cast<float2*>(&Cf[(long)(row + 8) * ldc + col]) =
                        make_float2(v2, v3);
            } else {
                uint2* Cp = reinterpret_cast<uint2*>(Cf);
                int ldcp = ldc >> 1;
                if (row < M && col < N) {
                    uint2 pk = split2(v0, v1);
                    Cp[(long)row * ldcp + (col >> 1)] = pk;
                    if (xdiag && row >= dlo && row < dhi)
                        xdiag[((long)zb * N_ + row) * KPACK + (col >> 1)] = pk;
                }
                if (row + 8 < M && col < N) {
                    uint2 pk = split2(v2, v3);
                    Cp[(long)(row + 8) * ldcp + (col >> 1)] = pk;
                    if (xdiag && row + 8 >= dlo && row + 8 < dhi)
                        xdiag[((long)zb * N_ + row + 8) * KPACK + (col >> 1)] = pk;
                }
            }
        }
    }
}

// ---------------- producer / glue kernels ------------------------------------
__global__ void transpose_x_h2(const float* __restrict__ x, uint2* __restrict__ o)
{
    long idx = (long)blockIdx.x * 256 + threadIdx.x;
    if (idx >= (long)M_ * KPACK) return;
    int pk = (int)(idx & (KPACK - 1));
    long m = idx >> 8;
    int b = (int)(m / N_);
    int n = (int)(m % N_);
    float2 v = *reinterpret_cast<const float2*>(&x[((long)n * B_ + b) * C_ + pk * 2]);
    o[idx] = h2split2(v.x, v.y);
}

__global__ void wsplit_h(const float* __restrict__ W, u32* __restrict__ o, int Ncols)
{
    long idx = (long)blockIdx.x * 256 + threadIdx.x;
    if (idx >= (long)Ncols * KPACK) return;
    int n  = (int)(idx % Ncols);
    int kp = (int)(idx / Ncols);
    float a = W[(long)(2 * kp)     * Ncols + n];
    float b = W[(long)(2 * kp + 1) * Ncols + n];
    o[(long)n * KPACK + kp] = h2pack(a, b);
}

__global__ void wsplit(const float* __restrict__ W, uint2* __restrict__ o, int Ncols)
{
    long idx = (long)blockIdx.x * 256 + threadIdx.x;
    if (idx >= (long)Ncols * KPACK) return;
    int n  = (int)(idx % Ncols);
    int kp = (int)(idx / Ncols);
    float a = W[(long)(2 * kp)     * Ncols + n];
    float b = W[(long)(2 * kp + 1) * Ncols + n];
    o[(long)n * KPACK + kp] = split2(a, b);
}

__global__ void wkG_split(const float* __restrict__ Wkv2, uint2* __restrict__ o)
{
    int idx = blockIdx.x * 256 + threadIdx.x;
    if (idx >= H_ * 512 * 32) return;
    int dp = idx & 31;
    int c  = (idx >> 5) & 511;
    int h  = idx >> 14;
    const float2 v = *reinterpret_cast<const float2*>(Wkv2 + (long)c * 1024 + h * 64 + 2 * dp);
    o[idx] = split2(v.x, v.y);
}

__global__ void wv_split(const float* __restrict__ Wkv2, uint2* __restrict__ o)
{
    int idx = blockIdx.x * 256 + threadIdx.x;
    if (idx >= 512 * KPACK) return;
    int n  = idx % 512;
    int kp = idx / 512;
    float a = Wkv2[(long)(2 * kp)     * 1024 + 512 + n];
    float b = Wkv2[(long)(2 * kp + 1) * 1024 + 512 + n];
    o[(long)n * KPACK + kp] = split2(a, b);
}

__global__ void vtrans_h(const u32* __restrict__ gv, u32* __restrict__ vt)
{
    long idx = (long)blockIdx.x * 256 + threadIdx.x;
    if (idx >= (long)B_ * F_ * PP_ * C_) return;
    int c  = (int)(idx & (C_ - 1));
    long r = idx >> 9;
    int pp = (int)(r % PP_);
    int bf = (int)(r / PP_);
    int b = bf / F_, f = bf % F_;
    long row0 = (long)b * N_ + (long)f * P_ + 2 * pp;
    u32 w0 = gv[row0 * KPACK + (c >> 1)];
    u32 w1 = gv[(row0 + 1) * KPACK + (c >> 1)];
    u32 lo = (c & 1) ? (w0 >> 16) : (w0 & 0xffffu);
    u32 hi = (c & 1) ? (w1 >> 16) : (w1 & 0xffffu);
    vt[((long)bf * C_ + c) * PP_ + pp] = lo | (hi << 16);
}

// softmax over P; fp32 in (float4 loads) -> fp16 single-plane out (uint2 stores)
#define SQ_ 230   // float4 quads per 920-elem row
__global__ void softmax_frames_h(const float* __restrict__ sc, u32* __restrict__ at)
{
    int rid = blockIdx.x;
    long bq = rid / F_;
    int  f  = rid % F_;
    const float4* row = reinterpret_cast<const float4*>(sc + bq * (long)N_ + (long)f * P_);
    uint2* orow = reinterpret_cast<uint2*>(at + bq * (long)(F_ * PP_) + (long)f * PP_);
    int t = threadIdx.x;

    float4 v[2];
    float mx = -1e30f;
#pragma unroll
    for (int i = 0; i < 2; i++) {
        int q = t + i * 128;
        if (q < SQ_) {
            v[i] = row[q];
            mx = fmaxf(mx, fmaxf(fmaxf(v[i].x, v[i].y), fmaxf(v[i].z, v[i].w)));
        } else {
            v[i] = make_float4(-1e30f, -1e30f, -1e30f, -1e30f);
        }
    }
    __shared__ float red[128];
    red[t] = mx; __syncthreads();
    for (int s = 64; s > 0; s >>= 1) {
        if (t < s) red[t] = fmaxf(red[t], red[t + s]);
        __syncthreads();
    }
    mx = red[0];
    __syncthreads();

    float sum = 0.f;
#pragma unroll
    for (int i = 0; i < 2; i++) {
        int q = t + i * 128;
        if (q < SQ_) {
            v[i].x = expf(v[i].x - mx);
            v[i].y = expf(v[i].y - mx);
            v[i].z = expf(v[i].z - mx);
            v[i].w = expf(v[i].w - mx);
            sum += (v[i].x + v[i].y) + (v[i].z + v[i].w);
        }
    }
    red[t] = sum; __syncthreads();
    for (int s = 64; s > 0; s >>= 1) {
        if (t < s) red[t] += red[t + s];
        __syncthreads();
    }
    float inv = 1.f / red[0];
#pragma unroll
    for (int i = 0; i < 2; i++) {
        int q = t + i * 128;
        if (q < SQ_) {
            uint2 o;
            o.x = h2pack(v[i].x * inv, v[i].y * inv);
            o.y = h2pack(v[i].z * inv, v[i].w * inv);
            orow[q] = o;
        }
    }
}

// Stage 2: dots + softmax + per-head weighted xo sum (xbar).
// xo tile loaded ONCE into smem as unpacked fp32 (10 KB), used by both phases.
__global__ void stage2_dots(const float* __restrict__ G,
                            const uint2* __restrict__ xo,
                            uint2* __restrict__ xbar,
                            float* __restrict__ attn2)
{
    __shared__ float sxo[F_ * C_];    // 2560 floats = 10 KB

    int m = blockIdx.x;
    int b = m / N_, s = m % N_;
    int w = threadIdx.x >> 5;     // head
    int l = threadIdx.x & 31;

    {
        const uint2* src = xo + (long)m * F_ * KPACK;
#pragma unroll
        for (int i = 0; i < 5; i++) {
            int idx = threadIdx.x + i * 256;
            float2 v = unsplit2(src[idx]);
            sxo[idx * 2]     = v.x;
            sxo[idx * 2 + 1] = v.y;
        }
    }
    __syncthreads();

    float4 g[4];
    const float4* Gr = reinterpret_cast<const float4*>(G + ((long)w * M_ + m) * C_);
#pragma unroll
    for (int j = 0; j < 4; j++) g[j] = Gr[l + 32 * j];

    float wgt[F_];
    float mx = -1e30f;
#pragma unroll
    for (int f = 0; f < F_; f++) {
        const float4* xr = reinterpret_cast<const float4*>(sxo + f * C_);
        float acc = 0.f;
#pragma unroll
        for (int j = 0; j < 4; j++) {
            float4 xv = xr[l + 32 * j];
            acc += g[j].x * xv.x + g[j].y * xv.y + g[j].z * xv.z + g[j].w * xv.w;
        }
#pragma unroll
        for (int o = 16; o > 0; o >>= 1) acc += __shfl_xor_sync(0xffffffffu, acc, o);
        wgt[f] = acc;
        mx = fmaxf(mx, acc);
    }
    float sum = 0.f;
#pragma unroll
    for (int f = 0; f < F_; f++) { wgt[f] = expf(wgt[f] - mx); sum += wgt[f]; }
    float inv = 1.f / sum;
#pragma unroll
    for (int f = 0; f < F_; f++) wgt[f] *= inv;

#pragma unroll
    for (int f = 0; f < F_; f++)
        if (l == f)
            attn2[(((long)b * H_ + w) * N_ + s) * F_ + f] = wgt[f];

    uint4* xr_out = reinterpret_cast<uint4*>(xbar + ((long)w * M_ + m) * KPACK);
#pragma unroll
    for (int j = 0; j < 4; j++) {
        float a0 = 0.f, a1 = 0.f, a2 = 0.f, a3 = 0.f;
#pragma unroll
        for (int f = 0; f < F_; f++) {
            const float4* xr = reinterpret_cast<const float4*>(sxo + f * C_);
            float4 xv = xr[l + 32 * j];
            a0 += wgt[f] * xv.x;
            a1 += wgt[f] * xv.y;
            a2 += wgt[f] * xv.z;
            a3 += wgt[f] * xv.w;
        }
        uint2 p0 = split2(a0, a1);
        uint2 p1 = split2(a2, a3);
        uint4 o; o.x = p0.x; o.y = p0.y; o.z = p1.x; o.w = p1.y;
        xr_out[l + 32 * j] = o;
    }
}

// ---------------- host launchers ----------------------------------------------
template<int EPI, int NT>
static void launch_sp(const uint2* A, const uint2* B, void* C,
                      int M, int N, int K, int ldap, int ldbp, int ldc,
                      int Z, int Z2,
                      long sA1, long sA2, long sB1, long sB2,
                      long sC1, long sC2, float alpha, const float* bias)
{
    const int BN = 32 * NT;
    const int smem = 3 * (TILE_A_U + BN * 16) * 8;
    dim3 grid((N + BN - 1) / BN, (M + 127) / 128, Z);
    gemm_sp<EPI, NT><<<grid, 256, smem>>>(A, B, C, M, N, K,
                                          ldap, ldbp, ldc,
                                          Z2, sA1, sA2, sB1, sB2, sC1, sC2,
                                          alpha, bias);
}

static void launch_h2(const uint2* A, const u32* B,
                      u32* qout, u32* kout, u32* vout,
                      int M, int N, int K, int ldap, int ldbp,
                      float alpha, int qcols)
{
    dim3 grid((N + 255) / 256, (M + 127) / 128, 1);
    gemm_h2<<<grid, 256, H2_SMEM>>>(A, B, qout, kout, vout, M, N, K,
                                    ldap, ldbp, alpha, qcols);
}

template<int EPI>
static void launch_h1(const u32* A, const u32* B, void* C, uint2* xdiag,
                      int M, int N, int K, int ldap, int ldbp, int ldc,
                      int Z, int Z2,
                      long sA1, long sA2, long sB1, long sB2,
                      long sC1, long sC2, float alpha)
{
    dim3 grid((N + 255) / 256, (M + 127) / 128, Z);
    gemm_h1<EPI><<<grid, H1_THREADS, H1_SMEM>>>(A, B, C, xdiag, M, N, K,
                                                ldap, ldbp, ldc,
                                                Z2, sA1, sA2, sB1, sB2, sC1, sC2,
                                                alpha);
}

extern "C" void kernel_launch(void* const* d_in, const int* in_sizes, int n_in,
                              void* d_out, int out_size)
{
    (void)in_sizes; (void)n_in; (void)out_size;
    const float* x      = (const float*)d_in[0];
    const float* W_qkv  = (const float*)d_in[1];
    const float* W_q2   = (const float*)d_in[2];
    const float* W_kv2  = (const float*)d_in[3];
    const float* W_proj = (const float*)d_in[4];
    const float* b_proj = (const float*)d_in[5];
    float* out = (float*)d_out;

    static bool attr_set = false;
    if (!attr_set) {
        const int smem8 = 3 * (TILE_A_U + 256 * 16) * 8;
        const int smem2 = 3 * (TILE_A_U +  64 * 16) * 8;
        cudaFuncSetAttribute(gemm_sp<0, 8>, cudaFuncAttributeMaxDynamicSharedMemorySize, smem8);
        cudaFuncSetAttribute(gemm_sp<1, 8>, cudaFuncAttributeMaxDynamicSharedMemorySize, smem8);
        cudaFuncSetAttribute(gemm_sp<2, 8>, cudaFuncAttributeMaxDynamicSharedMemorySize, smem8);
        cudaFuncSetAttribute(gemm_sp<1, 2>, cudaFuncAttributeMaxDynamicSharedMemorySize, smem2);
        cudaFuncSetAttribute(gemm_h2,    cudaFuncAttributeMaxDynamicSharedMemorySize, H2_SMEM);
        cudaFuncSetAttribute(gemm_h1<0>, cudaFuncAttributeMaxDynamicSharedMemorySize, H1_SMEM);
        cudaFuncSetAttribute(gemm_h1<1>, cudaFuncAttributeMaxDynamicSharedMemorySize, H1_SMEM);
        attr_set = true;
    }

    uint2 *pxh2, *pxosp, *pxdsp, *pq2sp, *pxbar, *pout2sp;
    uint2 *pwq2t, *pwkG, *pwvt, *pwprojt;
    u32 *pqh, *pkh, *pvh, *pvt, *pattn1, *pwqkvh;
    float *pscores, *pG;
    cudaGetSymbolAddress((void**)&pxh2,    g_xh2);
    cudaGetSymbolAddress((void**)&pqh,     g_qh);
    cudaGetSymbolAddress((void**)&pkh,     g_kh);
    cudaGetSymbolAddress((void**)&pvh,     g_vh);
    cudaGetSymbolAddress((void**)&pscores, g_scores);
    cudaGetSymbolAddress((void**)&pattn1,  g_attn1h);
    cudaGetSymbolAddress((void**)&pvt,     g_vt);
    cudaGetSymbolAddress((void**)&pxosp,   g_xosp);
    cudaGetSymbolAddress((void**)&pxdsp,   g_xdsp);
    cudaGetSymbolAddress((void**)&pq2sp,   g_q2sp);
    cudaGetSymbolAddress((void**)&pG,      g_G);
    cudaGetSymbolAddress((void**)&pxbar,   g_xbar);
    cudaGetSymbolAddress((void**)&pout2sp, g_out2sp);
    cudaGetSymbolAddress((void**)&pwqkvh,  g_wqkvh);
    cudaGetSymbolAddress((void**)&pwq2t,   g_wq2t);
    cudaGetSymbolAddress((void**)&pwkG,    g_wkG);
    cudaGetSymbolAddress((void**)&pwvt,    g_wvt);
    cudaGetSymbolAddress((void**)&pwprojt, g_wprojt);

    const int pb = (int)(((long)M_ * KPACK + 255) / 256);

    // #1 qkv weight -> fp16 single plane
    wsplit_h<<<(1536 * KPACK + 255) / 256, 256>>>(W_qkv, pwqkvh, 1536);
    // #2 xb -> fp16 hi/lo packets
    transpose_x_h2<<<pb, 256>>>(x, pxh2);
    // #3 qkv GEMM (Q cols 2-mult, K/V cols 1-mult); Q/K/V stored fp16 single
    launch_h2(pxh2, pwqkvh, pqh, pkh, pvh,
              M_, 3 * C_, C_, KPACK, KPACK, 1.0f, 512);
    // #4 scores[b] = scale * Q_b @ K_b^T  (plain fp16 1-mult, fp32 out)
    launch_h1<0>(pqh, pkh, pscores, nullptr, N_, N_, C_,
                 KPACK, KPACK, N_, B_, 1,
                 (long)N_ * KPACK, 0, (long)N_ * KPACK, 0,
                 (long)N_ * N_, 0, 0.125f);
    // #5 softmax over P -> attn1 fp16 single plane
    softmax_frames_h<<<M_ * F_, 128>>>(pscores, pattn1);
    // #6 V^T fp16
    vtrans_h<<<(int)(((long)B_ * F_ * PP_ * C_ + 255) / 256), 256>>>(pvh, pvt);
    // #7-#10 remaining weight splits (bf16x3 path)
    wsplit<<<( 512 * KPACK + 255) / 256, 256>>>(W_q2,   pwq2t,   512);
    wkG_split<<<(H_ * 512 * 32 + 255) / 256, 256>>>(W_kv2, pwkG);
    wv_split<<<(512 * KPACK + 255) / 256, 256>>>(W_kv2, pwvt);
    wsplit<<<( 512 * KPACK + 255) / 256, 256>>>(W_proj, pwprojt, 512);
    // #11 xo = attn1 @ V (plain fp16) -> bf16 packets + diag
    launch_h1<1>(pattn1, pvt, pxosp, pxdsp, N_, C_, P_,
                 F_ * PP_, PP_, F_ * C_, B_ * F_, F_,
                 (long)N_ * F_ * PP_, (long)PP_,
                 (long)F_ * C_ * PP_, (long)C_ * PP_,
                 (long)N_ * F_ * C_, (long)C_, 1.0f);
    // #12 q2 = (x_diag @ W_q2) * scale -> bf16 packets (bf16x3)
    launch_sp<1, 8>(pxdsp, pwq2t, pq2sp,
                    M_, C_, C_, KPACK, KPACK, C_,
                    1, 1, 0, 0, 0, 0, 0, 0, 0.125f, nullptr);
    // #13 G[h] = q2_h @ WkG_h^T (fp32, bf16x3)
    launch_sp<0, 8>(pq2sp, pwkG, pG,
                    M_, C_, DH_, KPACK, 32, C_, H_, H_,
                    0, 32, 0, (long)512 * 32,
                    0, (long)M_ * C_, 1.0f, nullptr);
    // #14 stage-2 dots + softmax + per-head weighted xo; attn2 into d_out tail
    stage2_dots<<<M_, 256>>>(pG, pxosp, pxbar, out + OUT1_);
    // #15 out2[:, h-block] = xbar_h @ Wv_h^T (narrow GEMM, bf16x3)
    launch_sp<1, 2>(pxbar, pwvt, pout2sp,
                    M_, DH_, C_, KPACK, KPACK, C_,
                    H_, H_,
                    0, (long)M_ * KPACK,
                    0, (long)DH_ * KPACK,
                    0, (long)DH_, 1.0f, nullptr);
    // #16 proj + bias + output permutation fused (bf16x3)
    launch_sp<2, 8>(pout2sp, pwprojt, out,
                    M_, C_, C_, KPACK, KPACK, C_,
                    1, 1, 0, 0, 0, 0, 0, 0, 1.0f, b_proj);
}